// round 9
// baseline (speedup 1.0000x reference)
#include <cuda_runtime.h>
#include <cuda_bf16.h>

#define NN 100000
#define EE 600000
#define NB_CHUNK 98  // ceil(NN/1024)

// ---- scratch (device globals; allocation is forbidden) ----
__device__ int   g_deg[NN];
__device__ int   g_off[NN];
__device__ int   g_cursor[NN];
__device__ float g_invdeg[NN];
__device__ int   g_csrc[EE];
__device__ volatile int g_blkTotal[NB_CHUNK];
__device__ volatile int g_blkFlag[NB_CHUNK];
__device__ float g_agg[(size_t)NN * 128];  // mean_nbr(x)
__device__ float g_h[(size_t)NN * 128];    // Pr = x@W1r, then layer-1 activations
__device__ float g_Q[(size_t)NN * 64];     // layer-2 GEMM out: [h@W2l | h@W2r]
__device__ int   g_is64;

// ---------------- init: zero degrees, reset scan flags, detect edge dtype ----
__global__ void k_init(const void* ei) {
    int i = blockIdx.x * blockDim.x + threadIdx.x;
    if (i < NN) g_deg[i] = 0;
    if (i < NB_CHUNK) g_blkFlag[i] = 0;
    if (i == 0) {
        const long long* p = (const long long*)ei;
        int ok = 1;
        for (int k = 0; k < 32; k++) {
            long long v = p[k];
            if (v < 0 || v >= NN) ok = 0;
        }
        g_is64 = ok;
    }
}

// ---------------- CSR role bodies (called from fused kernels) ----------------
__device__ __forceinline__ void count_body(int bid, const void* ei) {
    int e = bid * 256 + (int)threadIdx.x;
    if (e >= EE / 2) return;
    int d0, d1;
    if (g_is64) {
        longlong2 v = ((const longlong2*)ei)[EE / 2 + e];
        d0 = (int)v.x; d1 = (int)v.y;
    } else {
        int2 v = ((const int2*)ei)[EE / 2 + e];
        d0 = v.x; d1 = v.y;
    }
    atomicAdd(&g_deg[d0], 1);
    atomicAdd(&g_deg[d1], 1);
}

__device__ __forceinline__ void fill_body(int bid, const void* ei) {
    int e = bid * 256 + (int)threadIdx.x;
    if (e >= EE / 2) return;
    int s0, s1, d0, d1;
    if (g_is64) {
        longlong2 sv = ((const longlong2*)ei)[e];
        longlong2 dv = ((const longlong2*)ei)[EE / 2 + e];
        s0 = (int)sv.x; s1 = (int)sv.y; d0 = (int)dv.x; d1 = (int)dv.y;
    } else {
        int2 sv = ((const int2*)ei)[e];
        int2 dv = ((const int2*)ei)[EE / 2 + e];
        s0 = sv.x; s1 = sv.y; d0 = dv.x; d1 = dv.y;
    }
    g_csrc[atomicAdd(&g_cursor[d0], 1)] = s0;
    g_csrc[atomicAdd(&g_cursor[d1], 1)] = s1;
}

// agg[i] = invdeg[i] * sum_{j in N(i)} feat[j]  (feat stride 128 floats)
__device__ __forceinline__ void agg0_body(int bid, const float* __restrict__ feat,
                                          float* __restrict__ agg) {
    int node = bid * 8 + ((int)threadIdx.x >> 5);
    if (node >= NN) return;
    int lane = threadIdx.x & 31;
    int s = g_off[node], d = g_deg[node];
    const float4* F4 = (const float4*)feat;  // row stride = 32 float4
    float4 acc = make_float4(0.f, 0.f, 0.f, 0.f);
    int k = 0;
    for (; k + 1 < d; k += 2) {
        int j0 = g_csrc[s + k], j1 = g_csrc[s + k + 1];
        float4 v0 = F4[(size_t)j0 * 32 + lane];
        float4 v1 = F4[(size_t)j1 * 32 + lane];
        acc.x += v0.x + v1.x; acc.y += v0.y + v1.y;
        acc.z += v0.z + v1.z; acc.w += v0.w + v1.w;
    }
    if (k < d) {
        int j = g_csrc[s + k];
        float4 v = F4[(size_t)j * 32 + lane];
        acc.x += v.x; acc.y += v.y; acc.z += v.z; acc.w += v.w;
    }
    float sc = g_invdeg[node];
    acc.x *= sc; acc.y *= sc; acc.z *= sc; acc.w *= sc;
    ((float4*)agg)[(size_t)node * 32 + lane] = acc;
}

// Single-kernel exclusive scan of g_deg with parallel decoupled lookback.
__global__ __launch_bounds__(256) void k_scan() {
    __shared__ int tsum[256];
    __shared__ int tpre[256];
    __shared__ int red[256];
    __shared__ int sh_prefix;
    int b = blockIdx.x, t = threadIdx.x;
    int base = b * 1024;
    int v[4];
    int s = 0;
#pragma unroll
    for (int j = 0; j < 4; j++) {
        int i = base + t * 4 + j;
        v[j] = (i < NN) ? g_deg[i] : 0;
        s += v[j];
    }
    tsum[t] = s;
    __syncthreads();
    if (t == 0) {
        int acc = 0;
        for (int k = 0; k < 256; k++) {
            tpre[k] = acc;
            acc += tsum[k];
        }
        g_blkTotal[b] = acc;
        __threadfence();
        g_blkFlag[b] = 1;
    }
    int mine = 0;
    if (t < b) {
        while (g_blkFlag[t] == 0) {}
        mine = g_blkTotal[t];
    }
    red[t] = mine;
    __syncthreads();
    for (int o = 128; o > 0; o >>= 1) {
        if (t < o) red[t] += red[t + o];
        __syncthreads();
    }
    if (t == 0) sh_prefix = red[0];
    __syncthreads();
    int acc = sh_prefix + tpre[t];
#pragma unroll
    for (int j = 0; j < 4; j++) {
        int i = base + t * 4 + j;
        if (i < NN) {
            g_off[i] = acc;
            g_cursor[i] = acc;
            g_invdeg[i] = 1.0f / fmaxf((float)v[j], 1.0f);
        }
        acc += v[j];
    }
}

// ---------------- tf32 MMA GEMM body (double-buffered, K=128) ----------------
__device__ __forceinline__ unsigned f2tf(float f) {
    unsigned r;
    asm("cvt.rna.tf32.f32 %0, %1;" : "=r"(r) : "f"(f));
    return r;
}

__device__ __forceinline__ void mma8(float* c, const unsigned* a, const unsigned* b) {
    asm volatile(
        "mma.sync.aligned.m16n8k8.row.col.f32.tf32.tf32.f32 "
        "{%0,%1,%2,%3},{%4,%5,%6,%7},{%8,%9},{%0,%1,%2,%3};"
        : "+f"(c[0]), "+f"(c[1]), "+f"(c[2]), "+f"(c[3])
        : "r"(a[0]), "r"(a[1]), "r"(a[2]), "r"(a[3]), "r"(b[0]), "r"(b[1]));
}

// C[128-tile bid, BN] (+)= A[*,128] @ B[128,BN]
// DUALB: B tile is [B0 | B1] side by side, each [128, BN/2] row-major.
// EPI 0: plain store.  EPI 1: C = relu(acc + bias + C_prev)  (accumulate into C).
template <int BN, int WARPS_N, bool DUALB, int EPI>
__device__ __forceinline__ void gemm_body(
    int bid, const float* __restrict__ A, const float* __restrict__ B0,
    const float* __restrict__ B1, const float* __restrict__ bias,
    float* __restrict__ C, int ldc, unsigned* sh) {
    constexpr int WARPS_M = 8 / WARPS_N;
    constexpr int WM = 128 / WARPS_M;
    constexpr int WN = BN / WARPS_N;
    constexpr int MI = WM / 16;
    constexpr int NI = WN / 8;
    constexpr int LDA = 36;      // pad: conflict-free frag loads, 16B-aligned rows
    constexpr int LDB = BN + 8;  // pad: conflict-free frag loads, 16B-aligned rows
    constexpr int ASZ = 128 * LDA;
    constexpr int BSZ = 32 * LDB;
    constexpr int BLD = BN * 32 / 1024;  // B float4 slots per thread

    unsigned* As = sh;            // 2 * ASZ
    unsigned* Bs = sh + 2 * ASZ;  // 2 * BSZ

    int t = threadIdx.x;
    int lane = t & 31, w = t >> 5;
    int gid = lane >> 2, tid4 = lane & 3;
    int wm = (w / WARPS_N) * WM;
    int wn = (w % WARPS_N) * WN;
    int rowBase = bid * 128;

    float4 aR[4];
    float4 bR[BLD];

    auto ldTiles = [&](int k0) {
#pragma unroll
        for (int i = 0; i < 4; i++) {
            int idx = t + i * 256;
            int r = idx >> 3, seg = idx & 7;
            int grow = rowBase + r;
            aR[i] = (grow < NN) ? *(const float4*)&A[(size_t)grow * 128 + k0 + seg * 4]
                                : make_float4(0.f, 0.f, 0.f, 0.f);
        }
        if (DUALB) {
            constexpr int HALF = BN / 2;
#pragma unroll
            for (int i = 0; i < BLD; i++) {
                int idx = t + i * 256;
                int kk = idx / (BN / 4);
                int n = (idx % (BN / 4)) * 4;
                const float* src = (n < HALF) ? &B0[(size_t)(k0 + kk) * HALF + n]
                                              : &B1[(size_t)(k0 + kk) * HALF + n - HALF];
                bR[i] = *(const float4*)src;
            }
        } else {
#pragma unroll
            for (int i = 0; i < BLD; i++) {
                int idx = t + i * 256;
                int kk = idx / (BN / 4);
                int n = (idx % (BN / 4)) * 4;
                bR[i] = *(const float4*)&B0[(size_t)(k0 + kk) * BN + n];
            }
        }
    };

    auto stTiles = [&](int buf) {
        unsigned* Ab = As + buf * ASZ;
        unsigned* Bb = Bs + buf * BSZ;
#pragma unroll
        for (int i = 0; i < 4; i++) {
            int idx = t + i * 256;
            int r = idx >> 3, seg = idx & 7;
            uint4 u;
            u.x = f2tf(aR[i].x); u.y = f2tf(aR[i].y);
            u.z = f2tf(aR[i].z); u.w = f2tf(aR[i].w);
            *(uint4*)&Ab[r * LDA + seg * 4] = u;
        }
#pragma unroll
        for (int i = 0; i < BLD; i++) {
            int idx = t + i * 256;
            int kk = idx / (BN / 4);
            int n = (idx % (BN / 4)) * 4;
            uint4 u;
            u.x = f2tf(bR[i].x); u.y = f2tf(bR[i].y);
            u.z = f2tf(bR[i].z); u.w = f2tf(bR[i].w);
            *(uint4*)&Bb[kk * LDB + n] = u;
        }
    };

    float acc[MI][NI][4];
#pragma unroll
    for (int mi = 0; mi < MI; mi++)
#pragma unroll
        for (int ni = 0; ni < NI; ni++)
#pragma unroll
            for (int j = 0; j < 4; j++) acc[mi][ni][j] = 0.f;

    ldTiles(0);
    stTiles(0);
    __syncthreads();

#pragma unroll
    for (int k0 = 0; k0 < 128; k0 += 32) {
        int cur = (k0 >> 5) & 1;
        if (k0 < 96) ldTiles(k0 + 32);  // overlap next-tile loads with compute
        const unsigned* Ab = As + cur * ASZ;
        const unsigned* Bb = Bs + cur * BSZ;
#pragma unroll
        for (int ks = 0; ks < 32; ks += 8) {
            unsigned a[MI][4], b[NI][2];
#pragma unroll
            for (int mi = 0; mi < MI; mi++) {
                int r = wm + mi * 16 + gid;
                a[mi][0] = Ab[r * LDA + ks + tid4];
                a[mi][1] = Ab[(r + 8) * LDA + ks + tid4];
                a[mi][2] = Ab[r * LDA + ks + tid4 + 4];
                a[mi][3] = Ab[(r + 8) * LDA + ks + tid4 + 4];
            }
#pragma unroll
            for (int ni = 0; ni < NI; ni++) {
                int c = wn + ni * 8 + gid;
                b[ni][0] = Bb[(ks + tid4) * LDB + c];
                b[ni][1] = Bb[(ks + tid4 + 4) * LDB + c];
            }
#pragma unroll
            for (int mi = 0; mi < MI; mi++)
#pragma unroll
                for (int ni = 0; ni < NI; ni++) mma8(acc[mi][ni], a[mi], b[ni]);
        }
        if (k0 < 96) {
            __syncthreads();
            stTiles(cur ^ 1);
            __syncthreads();
        }
    }

    // epilogue
#pragma unroll
    for (int mi = 0; mi < MI; mi++) {
#pragma unroll
        for (int ni = 0; ni < NI; ni++) {
            int r0 = rowBase + wm + mi * 16 + gid;
            int c = wn + ni * 8 + 2 * tid4;
            float2 v0 = make_float2(acc[mi][ni][0], acc[mi][ni][1]);
            float2 v1 = make_float2(acc[mi][ni][2], acc[mi][ni][3]);
            if (EPI == 1) {
                float bx = bias[c], by = bias[c + 1];
                if (r0 < NN) {
                    float2 p = *(const float2*)&C[(size_t)r0 * ldc + c];
                    v0.x = fmaxf(v0.x + bx + p.x, 0.f);
                    v0.y = fmaxf(v0.y + by + p.y, 0.f);
                    *(float2*)&C[(size_t)r0 * ldc + c] = v0;
                }
                if (r0 + 8 < NN) {
                    float2 p = *(const float2*)&C[(size_t)(r0 + 8) * ldc + c];
                    v1.x = fmaxf(v1.x + bx + p.x, 0.f);
                    v1.y = fmaxf(v1.y + by + p.y, 0.f);
                    *(float2*)&C[(size_t)(r0 + 8) * ldc + c] = v1;
                }
            } else {
                if (r0 < NN) *(float2*)&C[(size_t)r0 * ldc + c] = v0;
                if (r0 + 8 < NN) *(float2*)&C[(size_t)(r0 + 8) * ldc + c] = v1;
            }
        }
    }
}

// ---------------- plain GEMM wrappers ----------------
template <int BN, int WARPS_N, bool DUALB, int EPI>
__global__ __launch_bounds__(256) void k_mma(
    const float* __restrict__ A, const float* __restrict__ B0,
    const float* __restrict__ B1, const float* __restrict__ bias,
    float* __restrict__ C, int ldc) {
    extern __shared__ unsigned sh[];
    gemm_body<BN, WARPS_N, DUALB, EPI>(blockIdx.x, A, B0, B1, bias, C, ldc, sh);
}

// ---------------- fused kernels: GEMM chunk + CSR/agg role ----------------
// ROLE 0 = count, 1 = fill, 2 = agg0
template <int ROLE>
__global__ __launch_bounds__(256) void k_fused(
    const float* __restrict__ A, const float* __restrict__ B0,
    float* __restrict__ C, const void* ei,
    const float* __restrict__ feat, float* __restrict__ agg,
    int gemmBase, int gemmCount) {
    extern __shared__ unsigned sh[];
    int b = blockIdx.x;
    if (b < gemmCount) {
        gemm_body<128, 4, false, 0>(gemmBase + b, A, B0, nullptr, nullptr, C, 128, sh);
    } else {
        int rb = b - gemmCount;
        if (ROLE == 0) count_body(rb, ei);
        else if (ROLE == 1) fill_body(rb, ei);
        else agg0_body(rb, feat, agg);
    }
}

// out = invdeg * sum_nbr Q[:, 0:32] + b2 + Q[:, 32:64]; Q stride 64
__global__ void k_agg2(const float* __restrict__ Q, const float* __restrict__ b2,
                       float* __restrict__ out) {
    int node = (blockIdx.x * blockDim.x + threadIdx.x) >> 5;
    if (node >= NN) return;
    int lane = threadIdx.x & 31;
    int s = g_off[node], d = g_deg[node];
    float acc = 0.f;
    int k = 0;
    for (; k + 1 < d; k += 2) {
        int j0 = g_csrc[s + k], j1 = g_csrc[s + k + 1];
        acc += Q[(size_t)j0 * 64 + lane] + Q[(size_t)j1 * 64 + lane];
    }
    if (k < d) acc += Q[(size_t)g_csrc[s + k] * 64 + lane];
    out[(size_t)node * 32 + lane] =
        acc * g_invdeg[node] + b2[lane] + Q[(size_t)node * 64 + 32 + lane];
}

extern "C" void kernel_launch(void* const* d_in, const int* in_sizes, int n_in,
                              void* d_out, int out_size) {
    const float* x   = (const float*)d_in[0];
    const void*  ei  = d_in[1];
    const float* W1l = (const float*)d_in[2];
    const float* b1  = (const float*)d_in[3];
    const float* W1r = (const float*)d_in[4];
    const float* W2l = (const float*)d_in[5];
    const float* b2  = (const float*)d_in[6];
    const float* W2r = (const float*)d_in[7];
    float* out = (float*)d_out;

    float *agg = nullptr, *h = nullptr, *Q = nullptr;
    cudaGetSymbolAddress((void**)&agg, g_agg);
    cudaGetSymbolAddress((void**)&h, g_h);
    cudaGetSymbolAddress((void**)&Q, g_Q);

    // dynamic smem: double-buffered As + Bs
    const int smem1 = 2 * (128 * 36 + 32 * (128 + 8)) * (int)sizeof(unsigned);  // 71680
    const int smem2 = 2 * (128 * 36 + 32 * (64 + 8)) * (int)sizeof(unsigned);   // 55296
    cudaFuncSetAttribute(k_fused<0>, cudaFuncAttributeMaxDynamicSharedMemorySize, smem1);
    cudaFuncSetAttribute(k_fused<1>, cudaFuncAttributeMaxDynamicSharedMemorySize, smem1);
    cudaFuncSetAttribute(k_fused<2>, cudaFuncAttributeMaxDynamicSharedMemorySize, smem1);
    cudaFuncSetAttribute(k_mma<128, 4, false, 1>,
                         cudaFuncAttributeMaxDynamicSharedMemorySize, smem1);
    cudaFuncSetAttribute(k_mma<64, 2, true, 0>,
                         cudaFuncAttributeMaxDynamicSharedMemorySize, smem2);

    const int MBLK = (NN + 127) / 128;          // 782 GEMM tiles for Pr
    const int CSRB = (EE / 2 + 255) / 256;      // 1172 count/fill blocks
    const int AGGB = (NN + 7) / 8;              // 12500 agg0 blocks
    const int G1 = 260, G2 = 260, G3 = MBLK - G1 - G2;  // Pr GEMM chunks

    // Pipeline: Pr = x@W1r (no graph dep) is spread across the three
    // latency/atomic-bound CSR/agg launches as leading GEMM-role blocks.
    k_init<<<(NN + 255) / 256, 256>>>(ei);
    k_fused<0><<<G1 + CSRB, 256, smem1>>>(x, W1r, h, ei, nullptr, nullptr, 0, G1);
    k_scan<<<NB_CHUNK, 256>>>();
    k_fused<1><<<G2 + CSRB, 256, smem1>>>(x, W1r, h, ei, nullptr, nullptr, G1, G2);
    k_fused<2><<<G3 + AGGB, 256, smem1>>>(x, W1r, h, nullptr, x, agg, G1 + G2, G3);

    // h = relu(agg @ W1l + Pr + b1)   (accumulating epilogue)
    k_mma<128, 4, false, 1><<<MBLK, 256, smem1>>>(agg, W1l, nullptr, b1, h, 128);

    // Layer 2: Q = h @ [W2l | W2r]; out = invdeg*agg(Q_l) + b2 + Q_r
    k_mma<64, 2, true, 0><<<MBLK, 256, smem2>>>(h, W2l, W2r, nullptr, Q, 64);
    k_agg2<<<AGGB, 256>>>(Q, b2, out);
}

// round 11
// speedup vs baseline: 2.4396x; 2.4396x over previous
#include <cuda_runtime.h>
#include <cuda_bf16.h>

#define NN 100000
#define EE 600000
#define NB_CHUNK 98  // ceil(NN/1024)

// ---- scratch (device globals; allocation is forbidden) ----
__device__ int   g_deg[NN];
__device__ int   g_off[NN];
__device__ int   g_cursor[NN];
__device__ float g_invdeg[NN];
__device__ int   g_csrc[EE];
__device__ volatile int g_blkTotal[NB_CHUNK];
__device__ volatile int g_blkFlag[NB_CHUNK];
__device__ float g_xr[(size_t)NN * 128];   // tf32-rounded x
__device__ float g_agg[(size_t)NN * 128];  // tf32-rounded mean_nbr(xr)
__device__ float g_h[(size_t)NN * 128];    // tf32-rounded layer-1 activations
__device__ float g_Q[(size_t)NN * 64];     // layer-2 GEMM out: [h@W2l | h@W2r]
__device__ float g_Wr[16384 * 2 + 4096 * 2];  // rounded [W1l|W1r|W2l|W2r]
__device__ int   g_is64;

__device__ __forceinline__ unsigned f2tf(float f) {
    unsigned r;
    asm("cvt.rna.tf32.f32 %0, %1;" : "=r"(r) : "f"(f));
    return r;
}
__device__ __forceinline__ float f2tff(float f) {
    return __uint_as_float(f2tf(f));
}

// ---------------- init: zero deg/flags, detect edge dtype, round weights ----
__global__ void k_init(const void* ei, const float* W1l, const float* W1r,
                       const float* W2l, const float* W2r) {
    int i = blockIdx.x * blockDim.x + threadIdx.x;
    if (i < NN) g_deg[i] = 0;
    if (i < NB_CHUNK) g_blkFlag[i] = 0;
    if (i < 16384) g_Wr[i] = f2tff(W1l[i]);
    else if (i < 32768) g_Wr[i] = f2tff(W1r[i - 16384]);
    else if (i < 36864) g_Wr[i] = f2tff(W2l[i - 32768]);
    else if (i < 40960) g_Wr[i] = f2tff(W2r[i - 36864]);
    if (i == 0) {
        const long long* p = (const long long*)ei;
        int ok = 1;
        for (int k = 0; k < 32; k++) {
            long long v = p[k];
            if (v < 0 || v >= NN) ok = 0;
        }
        g_is64 = ok;
    }
}

// ---------------- count + x-round fused (both lightweight roles) ----------
#define XB 6400  // x-round blocks: 6400*512 float4 slots >= 3.2M
__global__ __launch_bounds__(256) void k_count_round(const void* ei, const float* x) {
    int b = blockIdx.x, t = threadIdx.x;
    if (b < XB) {
        const float4* src = (const float4*)x;
        float4* dst = (float4*)g_xr;
#pragma unroll
        for (int j = 0; j < 2; j++) {
            int pos = b * 512 + j * 256 + t;
            if (pos < NN * 32) {
                float4 v = src[pos];
                v.x = f2tff(v.x); v.y = f2tff(v.y);
                v.z = f2tff(v.z); v.w = f2tff(v.w);
                dst[pos] = v;
            }
        }
        return;
    }
    int e = (b - XB) * 256 + t;
    if (e >= EE / 2) return;
    int d0, d1;
    if (g_is64) {
        longlong2 v = ((const longlong2*)ei)[EE / 2 + e];
        d0 = (int)v.x; d1 = (int)v.y;
    } else {
        int2 v = ((const int2*)ei)[EE / 2 + e];
        d0 = v.x; d1 = v.y;
    }
    atomicAdd(&g_deg[d0], 1);
    atomicAdd(&g_deg[d1], 1);
}

// Single-kernel exclusive scan of g_deg with parallel decoupled lookback.
__global__ __launch_bounds__(256) void k_scan() {
    __shared__ int tsum[256];
    __shared__ int tpre[256];
    __shared__ int red[256];
    __shared__ int sh_prefix;
    int b = blockIdx.x, t = threadIdx.x;
    int base = b * 1024;
    int v[4];
    int s = 0;
#pragma unroll
    for (int j = 0; j < 4; j++) {
        int i = base + t * 4 + j;
        v[j] = (i < NN) ? g_deg[i] : 0;
        s += v[j];
    }
    tsum[t] = s;
    __syncthreads();
    if (t == 0) {
        int acc = 0;
        for (int k = 0; k < 256; k++) {
            tpre[k] = acc;
            acc += tsum[k];
        }
        g_blkTotal[b] = acc;
        __threadfence();
        g_blkFlag[b] = 1;
    }
    int mine = 0;
    if (t < b) {
        while (g_blkFlag[t] == 0) {}
        mine = g_blkTotal[t];
    }
    red[t] = mine;
    __syncthreads();
    for (int o = 128; o > 0; o >>= 1) {
        if (t < o) red[t] += red[t + o];
        __syncthreads();
    }
    if (t == 0) sh_prefix = red[0];
    __syncthreads();
    int acc = sh_prefix + tpre[t];
#pragma unroll
    for (int j = 0; j < 4; j++) {
        int i = base + t * 4 + j;
        if (i < NN) {
            g_off[i] = acc;
            g_cursor[i] = acc;
            g_invdeg[i] = 1.0f / fmaxf((float)v[j], 1.0f);
        }
        acc += v[j];
    }
}

__global__ void k_fill(const void* ei) {
    int e = blockIdx.x * blockDim.x + threadIdx.x;
    if (e >= EE / 2) return;
    int s0, s1, d0, d1;
    if (g_is64) {
        longlong2 sv = ((const longlong2*)ei)[e];
        longlong2 dv = ((const longlong2*)ei)[EE / 2 + e];
        s0 = (int)sv.x; s1 = (int)sv.y; d0 = (int)dv.x; d1 = (int)dv.y;
    } else {
        int2 sv = ((const int2*)ei)[e];
        int2 dv = ((const int2*)ei)[EE / 2 + e];
        s0 = sv.x; s1 = sv.y; d0 = dv.x; d1 = dv.y;
    }
    g_csrc[atomicAdd(&g_cursor[d0], 1)] = s0;
    g_csrc[atomicAdd(&g_cursor[d1], 1)] = s1;
}

// ---------------- cp.async helpers ----------------
__device__ __forceinline__ void cp16(unsigned smem, const void* g, bool valid) {
    int sz = valid ? 16 : 0;
    asm volatile("cp.async.ca.shared.global [%0], [%1], 16, %2;\n"
                 :: "r"(smem), "l"(g), "r"(sz));
}
__device__ __forceinline__ void cp_commit() {
    asm volatile("cp.async.commit_group;\n" ::: "memory");
}
__device__ __forceinline__ void cp_wait0() {
    asm volatile("cp.async.wait_group 0;\n" ::: "memory");
}

__device__ __forceinline__ void mma8(float* c, const unsigned* a, const unsigned* b) {
    asm volatile(
        "mma.sync.aligned.m16n8k8.row.col.f32.tf32.tf32.f32 "
        "{%0,%1,%2,%3},{%4,%5,%6,%7},{%8,%9},{%0,%1,%2,%3};"
        : "+f"(c[0]), "+f"(c[1]), "+f"(c[2]), "+f"(c[3])
        : "r"(a[0]), "r"(a[1]), "r"(a[2]), "r"(a[3]), "r"(b[0]), "r"(b[1]));
}

// ---------------- tf32 MMA GEMM, cp.async double-buffered ----------------
// All A/B inputs must already be tf32-rounded (low 13 bits zero), so HMMA's
// truncation is identity.
// C[128-tile, BN] = A[*,KTOT] @ B[KTOT,BN]
// SPLITK: A = [A1 | A2] along K (each row-stride 128); B rows 0:128 from B0,
//         128:256 from B1 (each row-major [128, BN]).
// DUALB (!SPLITK): B tile is [B0 | B1] side by side, each [128, BN/2].
// RELU: epilogue adds bias, applies ReLU, and stores tf32-rounded.
template <int BN, int WARPS_N, int KTOT, bool SPLITK, bool RELU>
__global__ __launch_bounds__(256, 2) void k_mma(
    const float* __restrict__ A1, const float* __restrict__ A2,
    const float* __restrict__ B0, const float* __restrict__ B1,
    const float* __restrict__ bias, float* __restrict__ C, int ldc) {
    constexpr int WARPS_M = 8 / WARPS_N;
    constexpr int WM = 128 / WARPS_M;
    constexpr int WN = BN / WARPS_N;
    constexpr int MI = WM / 16;
    constexpr int NI = WN / 8;
    constexpr int LDA = 36;      // pad: conflict-free frag loads, 16B-aligned rows
    constexpr int LDB = BN + 8;  // pad: conflict-free frag loads, 16B-aligned rows
    constexpr int ASZ = 128 * LDA;
    constexpr int BSZ = 32 * LDB;
    constexpr int BLD = BN * 32 / 1024;  // B 16B-chunks per thread

    extern __shared__ unsigned sh[];
    unsigned* As = sh;            // 2 * ASZ
    unsigned* Bs = sh + 2 * ASZ;  // 2 * BSZ

    int t = threadIdx.x;
    int lane = t & 31, w = t >> 5;
    int gid = lane >> 2, tid4 = lane & 3;
    int wm = (w / WARPS_N) * WM;
    int wn = (w % WARPS_N) * WN;
    int rowBase = blockIdx.x * 128;

    unsigned shbase;
    asm("{ .reg .u64 tmp; cvta.to.shared.u64 tmp, %1; cvt.u32.u64 %0, tmp; }"
        : "=r"(shbase) : "l"((void*)sh));

    auto issueTile = [&](int k0, int buf) {
        const float* Ap = SPLITK ? (k0 < 128 ? A1 : A2) : A1;
        int ka = SPLITK ? (k0 & 127) : k0;
        unsigned Ab = shbase + (unsigned)(buf * ASZ) * 4u;
        unsigned Bb = shbase + (unsigned)((2 * ASZ) + buf * BSZ) * 4u;
#pragma unroll
        for (int i = 0; i < 4; i++) {
            int idx = t + i * 256;
            int r = idx >> 3, seg = idx & 7;
            int grow = rowBase + r;
            const float* src = &Ap[(size_t)grow * 128 + ka + seg * 4];
            cp16(Ab + (unsigned)(r * LDA + seg * 4) * 4u, src, grow < NN);
        }
        if (SPLITK) {
            const float* Wp = (k0 < 128) ? B0 : B1;
#pragma unroll
            for (int i = 0; i < BLD; i++) {
                int idx = t + i * 256;
                int kk = idx / (BN / 4);
                int n = (idx % (BN / 4)) * 4;
                cp16(Bb + (unsigned)(kk * LDB + n) * 4u,
                     &Wp[(size_t)(ka + kk) * BN + n], true);
            }
        } else {
            constexpr int HALF = BN / 2;
#pragma unroll
            for (int i = 0; i < BLD; i++) {
                int idx = t + i * 256;
                int kk = idx / (BN / 4);
                int n = (idx % (BN / 4)) * 4;
                const float* src = (n < HALF) ? &B0[(size_t)(k0 + kk) * HALF + n]
                                              : &B1[(size_t)(k0 + kk) * HALF + n - HALF];
                cp16(Bb + (unsigned)(kk * LDB + n) * 4u, src, true);
            }
        }
        cp_commit();
    };

    float acc[MI][NI][4];
#pragma unroll
    for (int mi = 0; mi < MI; mi++)
#pragma unroll
        for (int ni = 0; ni < NI; ni++)
#pragma unroll
            for (int j = 0; j < 4; j++) acc[mi][ni][j] = 0.f;

    issueTile(0, 0);

#pragma unroll
    for (int k0 = 0; k0 < KTOT; k0 += 32) {
        int cur = (k0 >> 5) & 1;
        cp_wait0();
        __syncthreads();
        if (k0 + 32 < KTOT) issueTile(k0 + 32, cur ^ 1);
        const unsigned* Ab = As + cur * ASZ;
        const unsigned* Bb = Bs + cur * BSZ;
#pragma unroll
        for (int ks = 0; ks < 32; ks += 8) {
            unsigned a[MI][4], b[NI][2];
#pragma unroll
            for (int mi = 0; mi < MI; mi++) {
                int r = wm + mi * 16 + gid;
                a[mi][0] = Ab[r * LDA + ks + tid4];
                a[mi][1] = Ab[(r + 8) * LDA + ks + tid4];
                a[mi][2] = Ab[r * LDA + ks + tid4 + 4];
                a[mi][3] = Ab[(r + 8) * LDA + ks + tid4 + 4];
            }
#pragma unroll
            for (int ni = 0; ni < NI; ni++) {
                int c = wn + ni * 8 + gid;
                b[ni][0] = Bb[(ks + tid4) * LDB + c];
                b[ni][1] = Bb[(ks + tid4 + 4) * LDB + c];
            }
#pragma unroll
            for (int mi = 0; mi < MI; mi++)
#pragma unroll
                for (int ni = 0; ni < NI; ni++) mma8(acc[mi][ni], a[mi], b[ni]);
        }
        // next iteration's cp_wait0+syncthreads guards buffer reuse
    }

    // epilogue
#pragma unroll
    for (int mi = 0; mi < MI; mi++) {
#pragma unroll
        for (int ni = 0; ni < NI; ni++) {
            int r0 = rowBase + wm + mi * 16 + gid;
            int c = wn + ni * 8 + 2 * tid4;
            float2 v0 = make_float2(acc[mi][ni][0], acc[mi][ni][1]);
            float2 v1 = make_float2(acc[mi][ni][2], acc[mi][ni][3]);
            if (RELU) {
                float bx = bias[c], by = bias[c + 1];
                v0.x = f2tff(fmaxf(v0.x + bx, 0.f));
                v0.y = f2tff(fmaxf(v0.y + by, 0.f));
                v1.x = f2tff(fmaxf(v1.x + bx, 0.f));
                v1.y = f2tff(fmaxf(v1.y + by, 0.f));
            }
            if (r0 < NN) *(float2*)&C[(size_t)r0 * ldc + c] = v0;
            if (r0 + 8 < NN) *(float2*)&C[(size_t)(r0 + 8) * ldc + c] = v1;
        }
    }
}

// ---------------- aggregations ----------------
// agg[i] = rna(invdeg[i] * sum_{j in N(i)} xr[j])   (stride 128 floats)
__global__ void k_agg0(const float* __restrict__ feat, float* __restrict__ agg) {
    int node = (blockIdx.x * blockDim.x + threadIdx.x) >> 5;
    if (node >= NN) return;
    int lane = threadIdx.x & 31;
    int s = g_off[node], d = g_deg[node];
    const float4* F4 = (const float4*)feat;  // row stride = 32 float4
    float4 acc = make_float4(0.f, 0.f, 0.f, 0.f);
    int k = 0;
    for (; k + 1 < d; k += 2) {
        int j0 = g_csrc[s + k], j1 = g_csrc[s + k + 1];
        float4 v0 = F4[(size_t)j0 * 32 + lane];
        float4 v1 = F4[(size_t)j1 * 32 + lane];
        acc.x += v0.x + v1.x; acc.y += v0.y + v1.y;
        acc.z += v0.z + v1.z; acc.w += v0.w + v1.w;
    }
    if (k < d) {
        int j = g_csrc[s + k];
        float4 v = F4[(size_t)j * 32 + lane];
        acc.x += v.x; acc.y += v.y; acc.z += v.z; acc.w += v.w;
    }
    float sc = g_invdeg[node];
    acc.x = f2tff(acc.x * sc); acc.y = f2tff(acc.y * sc);
    acc.z = f2tff(acc.z * sc); acc.w = f2tff(acc.w * sc);
    ((float4*)agg)[(size_t)node * 32 + lane] = acc;
}

// out = invdeg * sum_nbr Q[:, 0:32] + b2 + Q[:, 32:64]; Q stride 64
__global__ void k_agg2(const float* __restrict__ Q, const float* __restrict__ b2,
                       float* __restrict__ out) {
    int node = (blockIdx.x * blockDim.x + threadIdx.x) >> 5;
    if (node >= NN) return;
    int lane = threadIdx.x & 31;
    int s = g_off[node], d = g_deg[node];
    float acc = 0.f;
    int k = 0;
    for (; k + 1 < d; k += 2) {
        int j0 = g_csrc[s + k], j1 = g_csrc[s + k + 1];
        acc += Q[(size_t)j0 * 64 + lane] + Q[(size_t)j1 * 64 + lane];
    }
    if (k < d) acc += Q[(size_t)g_csrc[s + k] * 64 + lane];
    out[(size_t)node * 32 + lane] =
        acc * g_invdeg[node] + b2[lane] + Q[(size_t)node * 64 + 32 + lane];
}

extern "C" void kernel_launch(void* const* d_in, const int* in_sizes, int n_in,
                              void* d_out, int out_size) {
    const float* x   = (const float*)d_in[0];
    const void*  ei  = d_in[1];
    const float* W1l = (const float*)d_in[2];
    const float* b1  = (const float*)d_in[3];
    const float* W1r = (const float*)d_in[4];
    const float* W2l = (const float*)d_in[5];
    const float* b2  = (const float*)d_in[6];
    const float* W2r = (const float*)d_in[7];
    float* out = (float*)d_out;

    float *xr = nullptr, *agg = nullptr, *h = nullptr, *Q = nullptr, *Wr = nullptr;
    cudaGetSymbolAddress((void**)&xr, g_xr);
    cudaGetSymbolAddress((void**)&agg, g_agg);
    cudaGetSymbolAddress((void**)&h, g_h);
    cudaGetSymbolAddress((void**)&Q, g_Q);
    cudaGetSymbolAddress((void**)&Wr, g_Wr);

    // dynamic smem: double-buffered As + Bs
    const int smem1 = 2 * (128 * 36 + 32 * (128 + 8)) * (int)sizeof(unsigned);  // 71680
    const int smem2 = 2 * (128 * 36 + 32 * (64 + 8)) * (int)sizeof(unsigned);   // 55296
    cudaFuncSetAttribute(k_mma<128, 4, 256, true, true>,
                         cudaFuncAttributeMaxDynamicSharedMemorySize, smem1);
    cudaFuncSetAttribute(k_mma<64, 2, 128, false, false>,
                         cudaFuncAttributeMaxDynamicSharedMemorySize, smem2);

    const int CSRB = (EE / 2 + 255) / 256;  // 1172
    const int AGGB = (NN + 7) / 8;          // 12500
    const int MBLK = (NN + 127) / 128;      // 782

    // CSR build; x tf32-rounding rides along with the atomic-bound count.
    k_init<<<(NN + 255) / 256, 256>>>(ei, W1l, W1r, W2l, W2r);
    k_count_round<<<XB + CSRB, 256>>>(ei, x);
    k_scan<<<NB_CHUNK, 256>>>();
    k_fill<<<CSRB, 256>>>(ei);

    // Layer 1: agg = rna(mean_nbr(xr)); h = rna(relu([agg|xr] @ [W1l;W1r] + b1))
    k_agg0<<<AGGB, 256>>>(xr, agg);
    k_mma<128, 4, 256, true, true><<<MBLK, 256, smem1>>>(
        agg, xr, Wr, Wr + 16384, b1, h, 128);

    // Layer 2: Q = h @ [W2l | W2r]; out = invdeg*agg(Q_l) + b2 + Q_r
    k_mma<64, 2, 128, false, false><<<MBLK, 256, smem2>>>(
        h, nullptr, Wr + 32768, Wr + 36864, nullptr, Q, 64);
    k_agg2<<<AGGB, 256>>>(Q, b2, out);
}